// round 17
// baseline (speedup 1.0000x reference)
#include <cuda_runtime.h>
#include <cuda_fp16.h>
#include <math.h>
#include <stdint.h>

// Problem constants
#define BB 16      // batch
#define NA 128     // audio tokens
#define TT 10      // time steps
#define NV 196     // visual patches
#define DD 256     // feature dim
#define NPAD 208   // NV padded to multiple of 16 (symmetric 13/13 n8-tiles per wn)

// K-chunked pipeline: 4 chunks of K=64, one SMEM stage per chunk (no reuse)
#define KC 64
#define NCH 4
#define CH_ROWB 144                           // 64 fp16 = 128B + 16B pad
#define CH_A_BYTES (128 * CH_ROWB)            // 18432
#define CH_B_BYTES (NPAD * CH_ROWB)           // 29952
#define STAGE_BYTES (CH_A_BYTES + CH_B_BYTES) // 48384
#define OFF_RMAX (NCH * STAGE_BYTES)          // 193536
#define OFF_NEG  (OFF_RMAX + 2 * 128 * 4)
#define SMEM_DYN (OFF_NEG + 8 * 4 + 32)

// ---------------------------------------------------------------------------
// Device scratch (no allocations allowed)
// ---------------------------------------------------------------------------
__device__ __half g_a_f16[BB * NA * DD];       // normalized audio (incl 1/T)
__device__ __half g_v_f16[BB * TT * NV * DD];  // normalized visual
__device__ float g_clip_sum[BB * BB];
__device__ float g_negsum;

// ---------------------------------------------------------------------------
__device__ __forceinline__ uint32_t smem_u32(const void* p) {
    uint32_t a;
    asm("{ .reg .u64 t; cvta.to.shared.u64 t, %1; cvt.u32.u64 %0, t; }" : "=r"(a) : "l"(p));
    return a;
}
__device__ __forceinline__ void ldsm4(uint32_t* r, uint32_t addr) {
    asm volatile("ldmatrix.sync.aligned.m8n8.x4.shared.b16 {%0,%1,%2,%3}, [%4];"
                 : "=r"(r[0]), "=r"(r[1]), "=r"(r[2]), "=r"(r[3]) : "r"(addr));
}
__device__ __forceinline__ void ldsm2(uint32_t* r, uint32_t addr) {
    asm volatile("ldmatrix.sync.aligned.m8n8.x2.shared.b16 {%0,%1}, [%2];"
                 : "=r"(r[0]), "=r"(r[1]) : "r"(addr));
}
__device__ __forceinline__ void mma_f16(float* d, const uint32_t* a, const uint32_t* b) {
    asm volatile(
        "mma.sync.aligned.m16n8k16.row.col.f32.f16.f16.f32 "
        "{%0,%1,%2,%3}, {%4,%5,%6,%7}, {%8,%9}, {%0,%1,%2,%3};"
        : "+f"(d[0]), "+f"(d[1]), "+f"(d[2]), "+f"(d[3])
        : "r"(a[0]), "r"(a[1]), "r"(a[2]), "r"(a[3]), "r"(b[0]), "r"(b[1]));
}
__device__ __forceinline__ void cpasync16(uint32_t dst, const void* src) {
    asm volatile("cp.async.cg.shared.global [%0], [%1], 16;" :: "r"(dst), "l"(src));
}
__device__ __forceinline__ void cpasync16z(uint32_t dst, const void* src, uint32_t sz) {
    asm volatile("cp.async.cg.shared.global [%0], [%1], 16, %2;"
                 :: "r"(dst), "l"(src), "r"(sz));
}
__device__ __forceinline__ void cp_commit() {
    asm volatile("cp.async.commit_group;" ::: "memory");
}
template <int N> __device__ __forceinline__ void cp_wait() {
    asm volatile("cp.async.wait_group %0;" :: "n"(N) : "memory");
}

// ---------------------------------------------------------------------------
// Normalize: FOUR rows per warp (8 float4 loads in flight per thread).
// Zeroes scratch in block 0. Audio rows fold 1/temperature.
// ---------------------------------------------------------------------------
#define TOT_ROWS (BB * NA + BB * TT * NV)      // 33408 (audio first, then visual)
#define NORM_BLOCKS (TOT_ROWS / 32)            // 1044 (8 warps x 4 rows each)

__global__ void norm_all_kernel(const float* __restrict__ audio,
                                const float* __restrict__ visual,
                                const float* __restrict__ temp_ptr) {
    int tid = threadIdx.x;
    if (blockIdx.x == 0) {
        if (tid < BB * BB) g_clip_sum[tid] = 0.0f;
        if (tid == 0) g_negsum = 0.0f;
    }
    long wp = (blockIdx.x * (long)blockDim.x + tid) >> 5;   // warp id
    int lane = tid & 31;
    long r0 = 4 * wp;                                        // 4-row group
    // groups never straddle the audio/visual boundary (2048 % 4 == 0)
    const float* base;
    __half* obase;
    float scale;
    if (r0 < BB * NA) {
        base = audio; obase = g_a_f16; scale = 1.0f / (*temp_ptr);
    } else {
        base = visual - (long)BB * NA * DD; obase = g_v_f16 - (long)BB * NA * DD;
        scale = 1.0f;
    }
    float4 v[4][2];
    float ss[4];
#pragma unroll
    for (int r = 0; r < 4; r++) {
        const float4* s = reinterpret_cast<const float4*>(base + (r0 + r) * DD);
        v[r][0] = s[lane * 2];
        v[r][1] = s[lane * 2 + 1];
    }
#pragma unroll
    for (int r = 0; r < 4; r++) {
        ss[r] = v[r][0].x*v[r][0].x + v[r][0].y*v[r][0].y
              + v[r][0].z*v[r][0].z + v[r][0].w*v[r][0].w
              + v[r][1].x*v[r][1].x + v[r][1].y*v[r][1].y
              + v[r][1].z*v[r][1].z + v[r][1].w*v[r][1].w;
    }
#pragma unroll
    for (int off = 16; off >= 1; off >>= 1) {
#pragma unroll
        for (int r = 0; r < 4; r++)
            ss[r] += __shfl_xor_sync(0xffffffffu, ss[r], off);
    }
#pragma unroll
    for (int r = 0; r < 4; r++) {
        float inv = scale / fmaxf(sqrtf(ss[r]), 1e-12f);
        __half2 h[4];
        h[0] = __floats2half2_rn(v[r][0].x * inv, v[r][0].y * inv);
        h[1] = __floats2half2_rn(v[r][0].z * inv, v[r][0].w * inv);
        h[2] = __floats2half2_rn(v[r][1].x * inv, v[r][1].y * inv);
        h[3] = __floats2half2_rn(v[r][1].z * inv, v[r][1].w * inv);
        reinterpret_cast<uint4*>(obase + (r0 + r) * DD)[lane] = *reinterpret_cast<uint4*>(h);
    }
}

// ---------------------------------------------------------------------------
// Main: one block per (x,y,t). ldmatrix + mma.sync f16->f32, 128 x 208 x 256.
// 8 warps: 4 (M) x 2 (N); warp tile 32 x 104 = 2 x 13 m16n8k16 tiles (symmetric).
// K pipelined via cp.async: 4 chunks of K=64, all prefetched up front.
// ---------------------------------------------------------------------------
__global__ __launch_bounds__(256, 1) void sim_kernel() {
    extern __shared__ char sm[];
    const uint32_t sbase = smem_u32(sm);

    const int x = blockIdx.x, y = blockIdx.y, t = blockIdx.z;
    const int tid  = threadIdx.x;
    const int wid  = tid >> 5, lane = tid & 31;
    const int wm   = wid & 3;          // M group (SMSP id)
    const int wn   = wid >> 2;         // N group: cols wn*104..+103
    const int gid  = lane >> 2;
    const int tig  = lane & 3;

    // ---- issue all 4 K-chunk fills as independent cp.async groups ----
    const char* gA = (const char*)g_a_f16 + (size_t)x * NA * DD * 2;
    const char* gB = (const char*)g_v_f16 + (size_t)(y * TT + t) * NV * DD * 2;
#pragma unroll
    for (int c = 0; c < NCH; c++) {
        const uint32_t sb = sbase + c * STAGE_BYTES;
        const char* gAc = gA + c * (KC * 2);
        const char* gBc = gB + c * (KC * 2);
#pragma unroll
        for (int i = 0; i < 4; i++) {            // A: 128 rows x 8 segs
            int idx = tid + i * 256;
            int row = idx >> 3, seg = idx & 7;
            cpasync16(sb + row * CH_ROWB + seg * 16, gAc + row * 512 + seg * 16);
        }
#pragma unroll
        for (int i = 0; i < 7; i++) {            // B: 208 rows x 8 segs
            int idx = tid + i * 256;
            if (idx < NPAD * 8) {
                int n = idx >> 3, seg = idx & 7;
                int nc = (n < NV) ? n : (NV - 1);
                uint32_t sz = (n < NV) ? 16u : 0u;     // 0 -> HW zero fill
                cpasync16z(sb + CH_A_BYTES + n * CH_ROWB + seg * 16,
                           gBc + (size_t)nc * 512 + seg * 16, sz);
            }
        }
        cp_commit();
    }

    // ---- per-lane ldmatrix offsets (within a stage) ----
    const uint32_t aLane = (uint32_t)((wm * 32 + (lane & 15)) * CH_ROWB + (lane >> 4) * 16);
    const uint32_t bLane = (uint32_t)(CH_A_BYTES
                   + (wn * 104 + (lane & 7) + ((lane >> 4) & 1) * 8) * CH_ROWB
                   + ((lane >> 3) & 1) * 16);
    const uint32_t bLane2 = (uint32_t)(CH_A_BYTES
                   + (wn * 104 + 96 + (lane & 7)) * CH_ROWB
                   + ((lane >> 3) & 1) * 16);

    float acc[2][13][4];
#pragma unroll
    for (int mt = 0; mt < 2; mt++)
#pragma unroll
        for (int j = 0; j < 13; j++)
#pragma unroll
            for (int q = 0; q < 4; q++) acc[mt][j][q] = 0.0f;

    // ---- drain chunks in order; later-chunk fills overlap compute ----
#pragma unroll
    for (int c = 0; c < NCH; c++) {
        if (c == 0)      cp_wait<3>();
        else if (c == 1) cp_wait<2>();
        else if (c == 2) cp_wait<1>();
        else             cp_wait<0>();
        __syncthreads();

        const uint32_t sb = sbase + c * STAGE_BYTES;
        const uint32_t aAddr  = sb + aLane;
        const uint32_t bAddr  = sb + bLane;
        const uint32_t bAddr2 = sb + bLane2;
#pragma unroll
        for (int ks = 0; ks < 4; ks++) {
            const uint32_t koff = (uint32_t)ks * 32;   // 16 fp16 = 32B
            uint32_t a0[4], a1[4];
            ldsm4(a0, aAddr + koff);
            ldsm4(a1, aAddr + koff + 16 * CH_ROWB);
#pragma unroll
            for (int jp = 0; jp < 6; jp++) {
                uint32_t b[4];
                ldsm4(b, bAddr + koff + (uint32_t)jp * (16 * CH_ROWB));
                mma_f16(acc[0][2 * jp],     a0, b);
                mma_f16(acc[0][2 * jp + 1], a0, b + 2);
                mma_f16(acc[1][2 * jp],     a1, b);
                mma_f16(acc[1][2 * jp + 1], a1, b + 2);
            }
            uint32_t bl[2];
            ldsm2(bl, bAddr2 + koff);
            mma_f16(acc[0][12], a0, bl);
            mma_f16(acc[1][12], a1, bl);
        }
    }

    // ---- fused epilogue ----
    float rmax[2][2] = {{-1e30f, -1e30f}, {-1e30f, -1e30f}};
    float negsum = 0.0f;
#pragma unroll
    for (int mt = 0; mt < 2; mt++) {
#pragma unroll
        for (int j = 0; j < 13; j++) {
            int col = wn * 104 + j * 8 + tig * 2;
            float c0 = acc[mt][j][0], c1 = acc[mt][j][1];
            float c2 = acc[mt][j][2], c3 = acc[mt][j][3];
            // pad columns hold exact 0 -> contribute 0 to negsum
            float n0 = fminf(c0, 0.0f), n1 = fminf(c1, 0.0f);
            float n2 = fminf(c2, 0.0f), n3 = fminf(c3, 0.0f);
            negsum = fmaf(n0, n0, negsum); negsum = fmaf(n1, n1, negsum);
            negsum = fmaf(n2, n2, negsum); negsum = fmaf(n3, n3, negsum);
            if (col < NV)     { rmax[mt][0] = fmaxf(rmax[mt][0], c0);
                                rmax[mt][1] = fmaxf(rmax[mt][1], c2); }
            if (col + 1 < NV) { rmax[mt][0] = fmaxf(rmax[mt][0], c1);
                                rmax[mt][1] = fmaxf(rmax[mt][1], c3); }
        }
    }
#pragma unroll
    for (int off = 1; off <= 2; off <<= 1) {
#pragma unroll
        for (int mt = 0; mt < 2; mt++) {
            rmax[mt][0] = fmaxf(rmax[mt][0], __shfl_xor_sync(0xffffffffu, rmax[mt][0], off));
            rmax[mt][1] = fmaxf(rmax[mt][1], __shfl_xor_sync(0xffffffffu, rmax[mt][1], off));
        }
    }
#pragma unroll
    for (int off = 16; off >= 1; off >>= 1)
        negsum += __shfl_xor_sync(0xffffffffu, negsum, off);

    float* rowmax = reinterpret_cast<float*>(sm + OFF_RMAX);   // [2][128]
    float* negs   = reinterpret_cast<float*>(sm + OFF_NEG);    // [8]
    if (tig == 0) {
#pragma unroll
        for (int mt = 0; mt < 2; mt++) {
            int r = wm * 32 + mt * 16 + gid;
            rowmax[wn * 128 + r]     = rmax[mt][0];
            rowmax[wn * 128 + r + 8] = rmax[mt][1];
        }
    }
    if (lane == 0) negs[wid] = negsum;
    __syncthreads();

    if (tid < 128)
        rowmax[tid] = fmaxf(rowmax[tid], rowmax[128 + tid]);
    __syncthreads();
#pragma unroll
    for (int s = 64; s >= 1; s >>= 1) {
        if (tid < s) rowmax[tid] += rowmax[tid + s];
        __syncthreads();
    }
    if (tid == 0) {
        float ns = 0.0f;
#pragma unroll
        for (int i = 0; i < 8; i++) ns += negs[i];
        atomicAdd(&g_clip_sum[x * BB + y], rowmax[0]);
        atomicAdd(&g_negsum, ns);
    }
}

// ---------------------------------------------------------------------------
// Finalize: 16x16 clip sims -> InfoNCE + regularization -> 3 scalars
// ---------------------------------------------------------------------------
__global__ void finalize_kernel(const float* __restrict__ temp_ptr,
                                float* __restrict__ out, int out_size) {
    __shared__ float cs[BB][BB];
    __shared__ float lr[BB], lc[BB];
    int tid = threadIdx.x;
    if (tid < BB * BB)
        cs[tid >> 4][tid & 15] = g_clip_sum[tid] * (1.0f / (float)(NA * TT));
    __syncthreads();
    if (tid < BB) {
        int i = tid;
        float m = -1e30f, mc = -1e30f;
        for (int j = 0; j < BB; j++) { m = fmaxf(m, cs[i][j]); mc = fmaxf(mc, cs[j][i]); }
        float s = 0.0f, sc = 0.0f;
        for (int j = 0; j < BB; j++) { s += expf(cs[i][j] - m); sc += expf(cs[j][i] - mc); }
        lr[i] = m + logf(s);
        lc[i] = mc + logf(sc);
    }
    __syncthreads();
    if (tid == 0) {
        float lsum = 0.0f;
        for (int i = 0; i < BB; i++)
            lsum += -(cs[i][i] - lr[i]) - (cs[i][i] - lc[i]);
        float contrastive = 0.5f * (lsum / (float)BB);
        float l_nonneg = g_negsum
            / ((float)BB * (float)BB * (float)NA * (float)TT * (float)NV);
        float tv = *temp_ptr;
        float logt = logf(tv);
        float tl = fmaxf(-logt, 0.0f);             tl = tl * tl; tl = tl * tl;
        float th = fmaxf(logt - logf(3.0f), 0.0f); th = th * th; th = th * th;
        float reg = l_nonneg + tl + th;
        float total = contrastive + 0.3f * reg;
        out[0] = total;
        if (out_size > 1) out[1] = contrastive;
        if (out_size > 2) out[2] = reg;
    }
}

// ---------------------------------------------------------------------------
extern "C" void kernel_launch(void* const* d_in, const int* in_sizes, int n_in,
                              void* d_out, int out_size) {
    const float* audio  = (const float*)d_in[0];   // (16,128,256) f32
    const float* visual = (const float*)d_in[1];   // (16,10,196,256) f32
    const float* temp   = (const float*)d_in[2];   // scalar f32
    float* out = (float*)d_out;

    cudaFuncSetAttribute(sim_kernel, cudaFuncAttributeMaxDynamicSharedMemorySize, SMEM_DYN);

    norm_all_kernel<<<NORM_BLOCKS, 256>>>(audio, visual, temp);
    dim3 grid(BB, BB, TT);
    sim_kernel<<<grid, 256, SMEM_DYN>>>();
    finalize_kernel<<<1, 256>>>(temp, out, out_size);
}